// round 6
// baseline (speedup 1.0000x reference)
#include <cuda_runtime.h>
#include <cstdint>

// Problem constants (fixed shapes for SparseLinear_40278203302401)
#define BATCH 32
#define NNODES 100000
#define MNODES 100000
#define NNZ_TOTAL 3200000
#define BUCKET_CAP 96   // max in-degree supported; P(exceed) ~ 0 at mean 32, sd 5.7

// Scratch (device globals; no runtime allocation)
__device__ float g_xt[NNODES * BATCH];                 // x transposed (N, 32), 12.8 MB
__device__ int   g_cnt[MNODES];                        // per-dst edge counters
__device__ int2  g_bucket[(size_t)MNODES * BUCKET_CAP]; // {src, val-bits} per edge, 76.8 MB

// -------------------------------------------------------------------------
// Kernel 1: transpose x (B=32, N) -> x_t (N, 32), float4 both directions.
// Also clears the per-dst counters (block b clears cnt[b*32 .. b*32+31]).
// -------------------------------------------------------------------------
__global__ void __launch_bounds__(256)
k_transpose_x(const float* __restrict__ x, float* __restrict__ xt,
              int* __restrict__ cnt) {
    __shared__ float tile[32][33];
    const int n0 = blockIdx.x * 32;
    const int t  = threadIdx.x;
    const int r  = t >> 3;        // 0..31
    const int c4 = t & 7;         // 0..7

    // clear counters: 32 per block (grid = N/32 = M/32 = 3125)
    if (t < 32) cnt[n0 + t] = 0;

    // coalesced float4 read of x: row r = batch, cols n0 + c4*4 .. +3
    float4 v = *(const float4*)&x[r * NNODES + n0 + c4 * 4];
    tile[r][c4 * 4 + 0] = v.x;
    tile[r][c4 * 4 + 1] = v.y;
    tile[r][c4 * 4 + 2] = v.z;
    tile[r][c4 * 4 + 3] = v.w;
    __syncthreads();

    float4 o;
    o.x = tile[c4 * 4 + 0][r];
    o.y = tile[c4 * 4 + 1][r];
    o.z = tile[c4 * 4 + 2][r];
    o.w = tile[c4 * 4 + 3][r];
    *(float4*)&xt[(n0 + r) * BATCH + c4 * 4] = o;
}

// -------------------------------------------------------------------------
// Kernel 2: bucket edges by dst. One thread per edge.
//   pos = atomicAdd(cnt[dst], 1);  bucket[dst*96 + pos] = {src, val}
// Reads are fully coalesced; the 8B bucket store is random (one 32B sector).
// -------------------------------------------------------------------------
__global__ void __launch_bounds__(256)
k_scatter(const int* __restrict__ src, const int* __restrict__ dst,
          const float* __restrict__ val,
          int* __restrict__ cnt, int2* __restrict__ bucket) {
    const int e = blockIdx.x * blockDim.x + threadIdx.x;
    if (e >= NNZ_TOTAL) return;
    const int   s = src[e];
    const int   d = dst[e];
    const float v = val[e];
    const int pos = atomicAdd(&cnt[d], 1);
    if (pos < BUCKET_CAP) {
        bucket[(size_t)d * BUCKET_CAP + pos] = make_int2(s, __float_as_int(v));
    }
}

// -------------------------------------------------------------------------
// Kernel 3: gather-accumulate + fused transposed output.
// Block = 1024 threads = 32 warps; warp w owns node m = m0 + w.
// Each warp: read its <=96 bucket entries (coalesced, lane-parallel),
// shfl-broadcast each edge, gather xt[src*32 + lane] (128B coalesced),
// FMA into a register accumulator. Then 32x32 smem transpose and one
// coalesced 128B store per warp into out[b*M + m].
// -------------------------------------------------------------------------
__global__ void __launch_bounds__(1024)
k_gather(const int2* __restrict__ bucket, const int* __restrict__ cnt,
         const float* __restrict__ xt, const float* __restrict__ bias,
         float* __restrict__ out) {
    __shared__ float tile[32][33];
    const int m0   = blockIdx.x * 32;
    const int warp = threadIdx.x >> 5;
    const int lane = threadIdx.x & 31;
    const int m    = m0 + warp;

    const int c = cnt[m];                 // broadcast load
    const int2* __restrict__ row = &bucket[(size_t)m * BUCKET_CAP];

    float acc = 0.0f;
    for (int base = 0; base < c; base += 32) {
        const int take = min(32, c - base);
        int2 e = make_int2(0, 0);
        if (lane < take) e = row[base + lane];   // coalesced 8B loads

        for (int j = 0; j < take; j++) {
            const int   sj = __shfl_sync(0xffffffffu, e.x, j);
            const float vj = __uint_as_float(__shfl_sync(0xffffffffu, (unsigned)e.y, j));
            acc += vj * __ldg(&xt[sj * BATCH + lane]);
        }
    }
    acc += __ldg(&bias[m]);

    // tile[m_local][b] = y(m, b)
    tile[warp][lane] = acc;
    __syncthreads();

    // warp w writes batch b = w, columns m0..m0+31: coalesced 128B
    out[warp * MNODES + m0 + lane] = tile[lane][warp];
}

// -------------------------------------------------------------------------
// Launch
// Inputs (metadata order): x (B*N f32), indices (2*NNZ i32), values (NNZ f32),
//                          bias (M f32). Output: (B, M) f32.
// -------------------------------------------------------------------------
extern "C" void kernel_launch(void* const* d_in, const int* in_sizes, int n_in,
                              void* d_out, int out_size) {
    const float* x      = (const float*)d_in[0];
    const int*   indices= (const int*)d_in[1];
    const float* values = (const float*)d_in[2];
    const float* bias   = (const float*)d_in[3];
    float* out = (float*)d_out;

    const int* src = indices;              // row 0
    const int* dst = indices + NNZ_TOTAL;  // row 1

    float* xt;  cudaGetSymbolAddress((void**)&xt, g_xt);
    int*   cnt; cudaGetSymbolAddress((void**)&cnt, g_cnt);
    int2*  bkt; cudaGetSymbolAddress((void**)&bkt, g_bucket);

    // 1. transpose x + clear counters (N/32 = M/32 = 3125 blocks)
    k_transpose_x<<<NNODES / 32, 256>>>(x, xt, cnt);

    // 2. bucket edges by dst
    k_scatter<<<NNZ_TOTAL / 256, 256>>>(src, dst, values, cnt, bkt);

    // 3. gather-accumulate + write transposed output with bias
    k_gather<<<MNODES / 32, 1024>>>(bkt, cnt, xt, bias, out);
}